// round 6
// baseline (speedup 1.0000x reference)
#include <cuda_runtime.h>
#include <math.h>

// Problem constants
#define TT   64
#define BB   1024
#define DZc  256
#define DXc  64
#define DHc  1024

#define ROWS 8                 // batch rows per CTA
#define NCTA (BB / ROWS)       // 128 CTAs
#define NTH  512               // threads per CTA (16 warps)

// Dynamic shared memory layout (in floats)
#define OFF_Z     0                              // z            2048
#define OFF_KSUM  (OFF_Z    + ROWS * DZc)        // ksum         2048
#define OFF_XB    (OFF_KSUM + ROWS * DZc)        // xb           8192
#define OFF_HD    (OFF_XB   + ROWS * DHc)        // h duplicated 16384
#define OFF_PART  (OFF_HD   + 2 * ROWS * DHc)    // partials     16384
#define OFF_ZD    (OFF_PART + 2 * ROWS * DHc)    // z dup        4096
#define OFF_ZIND  (OFF_ZD   + 2 * ROWS * DZc)    // zin dup      4096
#define OFF_XSD   (OFF_ZIND + 2 * ROWS * DZc)    // x dup        1024
#define OFF_WT    (OFF_XSD  + 2 * ROWS * DXc)    // wt cache     1024
#define SMEM_FLOATS (OFF_WT + DHc)               // 55296 floats = 216 KB

typedef unsigned long long u64;

// packed f32x2 FMA: acc(2 lanes) += a * b   (one issue slot, 2 FMAs)
__device__ __forceinline__ void fma2(u64& acc, u64 a, u64 b)
{
    asm("fma.rn.f32x2 %0, %1, %2, %0;" : "+l"(acc) : "l"(a), "l"(b));
}
__device__ __forceinline__ float2 unpack2(u64 p)
{
    float2 v;
    asm("mov.b64 {%0, %1}, %2;" : "=f"(v.x), "=f"(v.y) : "l"(p));
    return v;
}

// 6-instr tanh: 1 - 2/(1+e^{2x}).  exp overflow/underflow saturate correctly.
__device__ __forceinline__ float fast_tanh(float x)
{
    const float e = __expf(2.0f * x);
    return 1.0f - 2.0f * __fdividef(1.0f, 1.0f + e);
}

// ---------------------------------------------------------------------------
// GEMM1 main (split-K 2-way, f32x2 col-packed, W double-buffered):
// partials for 8 rows x 4 cols.  indup_s: duplicated pairs, row stride 2*KTOT.
// ---------------------------------------------------------------------------
template <int KTOT>
__device__ __forceinline__ void gemm1_main(
    const float* indup_s, const float* __restrict__ W, float* out_part)
{
    const int lane = threadIdx.x & 255;
    const int half = threadIdx.x >> 8;
    const int c0   = lane * 4;
    const int kb   = half * (KTOT / 2);
    const int kend = kb + KTOT / 2;

    u64 a0[ROWS], a1[ROWS];
#pragma unroll
    for (int r = 0; r < ROWS; ++r) { a0[r] = 0ull; a1[r] = 0ull; }

    const float* Wp = W + kb * DHc + c0;
    ulonglong2 wc0 = *(const ulonglong2*)(Wp);
    ulonglong2 wc1 = *(const ulonglong2*)(Wp + DHc);

#pragma unroll 2
    for (int k = kb; k < kend; k += 2) {
        // prefetch next iteration's W (clamped on last iter: dummy re-read)
        const float* Wn = (k + 2 < kend) ? (Wp + 2 * DHc) : Wp;
        const ulonglong2 wn0 = *(const ulonglong2*)(Wn);
        const ulonglong2 wn1 = *(const ulonglong2*)(Wn + DHc);

#pragma unroll
        for (int r = 0; r < ROWS; ++r) {
            const ulonglong2 zp = *(const ulonglong2*)(indup_s + r * 2 * KTOT + 2 * k);
            fma2(a0[r], zp.x, wc0.x);
            fma2(a1[r], zp.x, wc0.y);
            fma2(a0[r], zp.y, wc1.x);
            fma2(a1[r], zp.y, wc1.y);
        }
        wc0 = wn0; wc1 = wn1;
        Wp += 2 * DHc;
    }

#pragma unroll
    for (int r = 0; r < ROWS; ++r) {
        ulonglong2 v; v.x = a0[r]; v.y = a1[r];
        *(ulonglong2*)(out_part + r * DHc + c0) = v;
    }
}

// ---------------------------------------------------------------------------
// Persistent kernel
// ---------------------------------------------------------------------------
__global__ void __launch_bounds__(NTH, 1)
ode_kernel(const float* __restrict__ z0, const float* __restrict__ t,
           const float* __restrict__ x,  const float* __restrict__ W1,
           const float* __restrict__ Wx, const float* __restrict__ wt,
           const float* __restrict__ b1, const float* __restrict__ W2,
           const float* __restrict__ b2, float* __restrict__ out)
{
    extern __shared__ float sm[];
    float* z_s    = sm + OFF_Z;
    float* ksum_s = sm + OFF_KSUM;
    float* xb_s   = sm + OFF_XB;
    float* hd_s   = sm + OFF_HD;     // h duplicated pairs [r][2k], stride 2048
    float* part_s = sm + OFF_PART;   // GEMM1: 2 halves; GEMM2: 8 segs
    float* zd_s   = sm + OFF_ZD;     // z duplicated pairs   [r][2j]
    float* zind_s = sm + OFF_ZIND;   // zin duplicated pairs [r][2j]
    float* xsd_s  = sm + OFF_XSD;    // x duplicated pairs   [r][2d]
    float* wt_s   = sm + OFF_WT;     // wt cache
    float* pa_s   = part_s;                  // GEMM1 half-0 partial
    float* pb_s   = part_s + ROWS * DHc;     // GEMM1 half-1 partial

    const int tid  = threadIdx.x;
    const int half = tid >> 8;
    const int row0 = blockIdx.x * ROWS;

    // cache wt; load z0 block into z_s and zd_s
    wt_s[tid] = wt[tid];
    wt_s[tid + NTH] = wt[tid + NTH];
#pragma unroll
    for (int i = 0; i < (ROWS * DZc) / NTH; ++i) {
        const int idx = i * NTH + tid;                 // r*DZc + j
        const float v = z0[row0 * DZc + idx];
        z_s[idx] = v;
        *(float2*)(zd_s + ((idx >> 8) << 9) + ((idx & 255) << 1)) = make_float2(v, v);
    }
    __syncthreads();

    for (int step = 0; step < TT - 1; ++step) {
        const float t0 = __ldg(t + step);
        const float t1 = __ldg(t + step + 1);
        const float hstep = t1 - t0;
        const float tmid  = t0 + 0.5f * hstep;

        // stage x[step] rows (512 floats) as duplicated pairs
        {
            const float v = x[(step * BB + row0) * DXc + tid];   // r = tid>>6, d = tid&63
            *(float2*)(xsd_s + ((tid >> 6) << 7) + ((tid & 63) << 1)) = make_float2(v, v);
        }
        __syncthreads();

        // ---- xb = x @ Wx + b1 (split-K over DX=64) ----
        gemm1_main<DXc>(xsd_s, Wx, half ? pb_s : pa_s);
        __syncthreads();
#pragma unroll
        for (int i = 0; i < 4; ++i) {
            const int pos = tid + i * NTH;                 // float4 index [0,2048)
            const int off = (pos >> 8) * DHc + (pos & 255) * 4;
            const float4 a  = *(const float4*)(pa_s + off);
            const float4 b  = *(const float4*)(pb_s + off);
            const float4 bb = *(const float4*)(b1 + (pos & 255) * 4);
            float4 v;
            v.x = a.x + b.x + bb.x;  v.y = a.y + b.y + bb.y;
            v.z = a.z + b.z + bb.z;  v.w = a.w + b.w + bb.w;
            *(float4*)(xb_s + off) = v;
        }
        __syncthreads();

        // ---- 4 RK4 sub-evaluations ----
#pragma unroll 1
        for (int sub = 0; sub < 4; ++sub) {
            const float ts = (sub == 0) ? t0 : (sub == 3 ? t1 : tmid);
            const float* zi = (sub == 0) ? zd_s : zind_s;

            // GEMM1 main: partials into pa (half0) / pb (half1)
            gemm1_main<DZc>(zi, W1, half ? pb_s : pa_s);
            __syncthreads();

            // GEMM1 combine + tanh -> h duplicated (all threads)
#pragma unroll
            for (int i = 0; i < 4; ++i) {
                const int pos = tid + i * NTH;
                const int c   = (pos & 255) * 4;
                const int r   = pos >> 8;
                const int off = r * DHc + c;
                const float4 a   = *(const float4*)(pa_s + off);
                const float4 b   = *(const float4*)(pb_s + off);
                const float4 xbv = *(const float4*)(xb_s + off);
                const float4 wtv = *(const float4*)(wt_s + c);
                const float h0 = fast_tanh(a.x + b.x + xbv.x + ts * wtv.x);
                const float h1 = fast_tanh(a.y + b.y + xbv.y + ts * wtv.y);
                const float h2 = fast_tanh(a.z + b.z + xbv.z + ts * wtv.z);
                const float h3 = fast_tanh(a.w + b.w + xbv.w + ts * wtv.w);
                float* dst = hd_s + r * (2 * DHc) + 2 * c;
                *(float4*)(dst)     = make_float4(h0, h0, h1, h1);
                *(float4*)(dst + 4) = make_float4(h2, h2, h3, h3);
            }
            __syncthreads();

            // GEMM2 main (split-K 8-way, f32x2 col-packed, W2 double-buffered)
            {
                const int cg   = tid & 63;
                const int kseg = tid >> 6;
                const int j0   = cg * 4;
                const int kb   = kseg * (DHc / 8);
                const int kend = kb + DHc / 8;
                u64 a01[ROWS], a23[ROWS];
#pragma unroll
                for (int r = 0; r < ROWS; ++r) { a01[r] = 0ull; a23[r] = 0ull; }

                const float* Wp = W2 + kb * DZc + j0;
                ulonglong2 wcA = *(const ulonglong2*)(Wp);
                ulonglong2 wcB = *(const ulonglong2*)(Wp + DZc);

#pragma unroll 2
                for (int k = kb; k < kend; k += 2) {
                    const float* Wn = (k + 2 < kend) ? (Wp + 2 * DZc) : Wp;
                    const ulonglong2 wnA = *(const ulonglong2*)(Wn);
                    const ulonglong2 wnB = *(const ulonglong2*)(Wn + DZc);
#pragma unroll
                    for (int r = 0; r < ROWS; ++r) {
                        const ulonglong2 hp = *(const ulonglong2*)(hd_s + r * (2 * DHc) + 2 * k);
                        fma2(a01[r], hp.x, wcA.x);
                        fma2(a23[r], hp.x, wcA.y);
                        fma2(a01[r], hp.y, wcB.x);
                        fma2(a23[r], hp.y, wcB.y);
                    }
                    wcA = wnA; wcB = wnB;
                    Wp += 2 * DZc;
                }
                // store partial [kseg][r][j0..j0+3]
#pragma unroll
                for (int r = 0; r < ROWS; ++r) {
                    const float2 v01 = unpack2(a01[r]);
                    const float2 v23 = unpack2(a23[r]);
                    *(float4*)(part_s + kseg * (ROWS * DZc) + r * DZc + j0) =
                        make_float4(v01.x, v01.y, v23.x, v23.y);
                }
            }
            __syncthreads();

            // combine 8 partials + RK4 update (thread owns row r, cols j0..j0+3)
            {
                const int r  = tid >> 6;
                const int j0 = (tid & 63) * 4;
                const int base = r * DZc + j0;
                float4 s = *(const float4*)(part_s + base);
#pragma unroll
                for (int seg = 1; seg < 8; ++seg) {
                    const float4 p = *(const float4*)(part_s + seg * (ROWS * DZc) + base);
                    s.x += p.x; s.y += p.y; s.z += p.z; s.w += p.w;
                }
                const float4 bb = *(const float4*)(b2 + j0);
                const float v0 = s.x + bb.x, v1 = s.y + bb.y;
                const float v2 = s.z + bb.z, v3 = s.w + bb.w;

                const float4 zv = *(const float4*)(z_s + base);
                float* dup = zind_s + r * (2 * DZc) + 2 * j0;

                if (sub == 0) {
                    *(float4*)(ksum_s + base) = make_float4(v0, v1, v2, v3);
                    const float c = 0.5f * hstep;
                    const float n0 = zv.x + c * v0, n1 = zv.y + c * v1;
                    const float n2 = zv.z + c * v2, n3 = zv.w + c * v3;
                    *(float4*)(dup)     = make_float4(n0, n0, n1, n1);
                    *(float4*)(dup + 4) = make_float4(n2, n2, n3, n3);
                } else if (sub == 1 || sub == 2) {
                    float4 ks = *(const float4*)(ksum_s + base);
                    ks.x += 2.f * v0; ks.y += 2.f * v1;
                    ks.z += 2.f * v2; ks.w += 2.f * v3;
                    *(float4*)(ksum_s + base) = ks;
                    const float c = (sub == 1) ? 0.5f * hstep : hstep;
                    const float n0 = zv.x + c * v0, n1 = zv.y + c * v1;
                    const float n2 = zv.z + c * v2, n3 = zv.w + c * v3;
                    *(float4*)(dup)     = make_float4(n0, n0, n1, n1);
                    *(float4*)(dup + 4) = make_float4(n2, n2, n3, n3);
                } else {
                    const float4 ks = *(const float4*)(ksum_s + base);
                    const float c = hstep * (1.f / 6.f);
                    const float n0 = zv.x + c * (ks.x + v0);
                    const float n1 = zv.y + c * (ks.y + v1);
                    const float n2 = zv.z + c * (ks.z + v2);
                    const float n3 = zv.w + c * (ks.w + v3);
                    *(float4*)(z_s + base) = make_float4(n0, n1, n2, n3);
                    float* zdup = zd_s + r * (2 * DZc) + 2 * j0;
                    *(float4*)(zdup)     = make_float4(n0, n0, n1, n1);
                    *(float4*)(zdup + 4) = make_float4(n2, n2, n3, n3);
                }
            }
            __syncthreads();
        }
    }

    // write z_final
#pragma unroll
    for (int i = 0; i < (ROWS * DZc) / NTH; ++i)
        out[row0 * DZc + i * NTH + tid] = z_s[i * NTH + tid];
}

extern "C" void kernel_launch(void* const* d_in, const int* in_sizes, int n_in,
                              void* d_out, int out_size)
{
    const float* z0 = (const float*)d_in[0];
    const float* t  = (const float*)d_in[1];
    const float* x  = (const float*)d_in[2];
    const float* W1 = (const float*)d_in[3];
    const float* Wx = (const float*)d_in[4];
    const float* wt = (const float*)d_in[5];
    const float* b1 = (const float*)d_in[6];
    const float* W2 = (const float*)d_in[7];
    const float* b2 = (const float*)d_in[8];
    float* out = (float*)d_out;

    const size_t smem = SMEM_FLOATS * sizeof(float);   // ~216 KB
    cudaFuncSetAttribute(ode_kernel,
                         cudaFuncAttributeMaxDynamicSharedMemorySize, (int)smem);
    ode_kernel<<<NCTA, NTH, smem>>>(z0, t, x, W1, Wx, wt, b1, W2, b2, out);
}

// round 7
// speedup vs baseline: 1.0832x; 1.0832x over previous
#include <cuda_runtime.h>

// Problem constants
#define TT   64
#define BB   1024
#define DZc  256
#define DXc  64
#define DHc  1024

#define ROWS 8                 // batch rows per CTA
#define NCTA (BB / ROWS)       // 128 CTAs
#define NTH  512               // threads per CTA (16 warps)

// Packed weight scratch (k-pair interleaved): W*[k][c] -> Wp[k/2][c][2]
__device__ float g_W1p[DZc * DHc];   // 1 MB
__device__ float g_Wxp[DXc * DHc];   // 256 KB
__device__ float g_W2p[DHc * DZc];   // 1 MB

// Dynamic shared memory layout (floats)
#define OFF_Z    0                             // 2048
#define OFF_ZIN  (OFF_Z    + ROWS * DZc)       // 2048
#define OFF_KSUM (OFF_ZIN  + ROWS * DZc)       // 2048
#define OFF_XB   (OFF_KSUM + ROWS * DZc)       // 8192
#define OFF_H    (OFF_XB   + ROWS * DHc)       // 8192 (plain layout)
#define OFF_PART (OFF_H    + ROWS * DHc)       // 4 * 2048 = 8192
#define OFF_XS   (OFF_PART + 4 * ROWS * DZc)   // 512
#define OFF_WT   (OFF_XS   + ROWS * DXc)       // 1024
#define OFF_B1   (OFF_WT   + DHc)              // 1024
#define OFF_B2   (OFF_B1   + DHc)              // 256
#define SMEM_FLOATS (OFF_B2 + DZc)             // 33536 floats = 131 KB

typedef unsigned long long u64;

// packed f32x2 FMA: acc(2 lanes) += a * b
__device__ __forceinline__ void fma2(u64& acc, u64 a, u64 b)
{
    asm("fma.rn.f32x2 %0, %1, %2, %0;" : "+l"(acc) : "l"(a), "l"(b));
}
__device__ __forceinline__ float2 unpack2(u64 p)
{
    float2 v;
    asm("mov.b64 {%0, %1}, %2;" : "=f"(v.x), "=f"(v.y) : "l"(p));
    return v;
}

// 1 - 2/(1+e^{2x}); saturates correctly at +/-inf of exp.
__device__ __forceinline__ float fast_tanh(float x)
{
    const float e = __expf(2.0f * x);
    return 1.0f - 2.0f * __fdividef(1.0f, 1.0f + e);
}

// ---------------------------------------------------------------------------
// Weight pack kernel: Wp[kp][c][2] = (W[2kp][c], W[2kp+1][c])
// ---------------------------------------------------------------------------
__global__ void pack_kernel(const float* __restrict__ W1,
                            const float* __restrict__ Wx,
                            const float* __restrict__ W2)
{
    const int i = blockIdx.x * blockDim.x + threadIdx.x;   // [0, 262144)
    {   // W1p: row = 2048 floats (1024 cols x 2)
        const int kp = i >> 11, rem = i & 2047;
        const int c = rem >> 1, par = rem & 1;
        g_W1p[i] = W1[(2 * kp + par) * DHc + c];
    }
    {   // W2p: row = 512 floats (256 cols x 2)
        const int kp = i >> 9, rem = i & 511;
        const int j = rem >> 1, par = rem & 1;
        g_W2p[i] = W2[(2 * kp + par) * DZc + j];
    }
    if (i < DXc * DHc) {   // Wxp
        const int kp = i >> 11, rem = i & 2047;
        const int c = rem >> 1, par = rem & 1;
        g_Wxp[i] = Wx[(2 * kp + par) * DHc + c];
    }
}

// ---------------------------------------------------------------------------
// k-packed GEMM accumulate: thread owns cols (c0, c0+1), all 8 rows, full K.
// in_s plain [r][KTOT]; Wp packed [kp][1024][2].  acc lanes = (even-k, odd-k).
// ---------------------------------------------------------------------------
template <int KTOT>
__device__ __forceinline__ void gemm1_acc(
    const float* in_s, const float* __restrict__ Wp, u64* a0, u64* a1)
{
    const int c0 = threadIdx.x * 2;
#pragma unroll
    for (int r = 0; r < ROWS; ++r) { a0[r] = 0ull; a1[r] = 0ull; }

    const float* wb = Wp + c0 * 2;
#pragma unroll 2
    for (int k = 0; k < KTOT; k += 4) {
        // wA: kpair(k,k+1) for cols c0,c1 ; wB: kpair(k+2,k+3)
        const ulonglong2 wA = *(const ulonglong2*)(wb + (k >> 1) * (2 * DHc));
        const ulonglong2 wB = *(const ulonglong2*)(wb + ((k >> 1) + 1) * (2 * DHc));
#pragma unroll
        for (int r = 0; r < ROWS; ++r) {
            const ulonglong2 zp = *(const ulonglong2*)(in_s + r * KTOT + k);  // broadcast
            fma2(a0[r], zp.x, wA.x);
            fma2(a1[r], zp.x, wA.y);
            fma2(a0[r], zp.y, wB.x);
            fma2(a1[r], zp.y, wB.y);
        }
    }
}

// ---------------------------------------------------------------------------
// Persistent kernel
// ---------------------------------------------------------------------------
__global__ void __launch_bounds__(NTH, 1)
ode_kernel(const float* __restrict__ z0, const float* __restrict__ t,
           const float* __restrict__ x,  const float* __restrict__ wt,
           const float* __restrict__ b1, const float* __restrict__ b2,
           float* __restrict__ out)
{
    extern __shared__ float sm[];
    float* z_s    = sm + OFF_Z;
    float* zin_s  = sm + OFF_ZIN;
    float* ksum_s = sm + OFF_KSUM;
    float* xb_s   = sm + OFF_XB;
    float* h_s    = sm + OFF_H;      // plain [r][DH]
    float* part_s = sm + OFF_PART;   // 4 segs of [r][DZ]
    float* xs_s   = sm + OFF_XS;     // plain [r][DX]
    float* wt_s   = sm + OFF_WT;
    float* b1_s   = sm + OFF_B1;
    float* b2_s   = sm + OFF_B2;

    const int tid  = threadIdx.x;
    const int c0   = tid * 2;        // GEMM1 column pair
    const int row0 = blockIdx.x * ROWS;

    // cache small vectors; load z0 block
    wt_s[tid]       = wt[tid];
    wt_s[tid + NTH] = wt[tid + NTH];
    b1_s[tid]       = b1[tid];
    b1_s[tid + NTH] = b1[tid + NTH];
    if (tid < DZc) b2_s[tid] = b2[tid];
#pragma unroll
    for (int i = 0; i < (ROWS * DZc) / NTH; ++i)
        z_s[i * NTH + tid] = z0[row0 * DZc + i * NTH + tid];
    __syncthreads();

    for (int step = 0; step < TT - 1; ++step) {
        const float t0 = __ldg(t + step);
        const float t1 = __ldg(t + step + 1);
        const float hstep = t1 - t0;
        const float tmid  = t0 + 0.5f * hstep;

        // stage x[step] rows plain [r][DX]
        xs_s[tid] = x[(step * BB + row0) * DXc + tid];
        __syncthreads();

        // ---- xb = x @ Wx + b1 (no split; epilogue writes xb_s directly) ----
        {
            u64 a0[ROWS], a1[ROWS];
            gemm1_acc<DXc>(xs_s, g_Wxp, a0, a1);
            const float bb0 = b1_s[c0], bb1 = b1_s[c0 + 1];
#pragma unroll
            for (int r = 0; r < ROWS; ++r) {
                const float2 v0 = unpack2(a0[r]);
                const float2 v1 = unpack2(a1[r]);
                *(float2*)(xb_s + r * DHc + c0) =
                    make_float2(v0.x + v0.y + bb0, v1.x + v1.y + bb1);
            }
        }
        __syncthreads();

        // ---- 4 RK4 sub-evaluations ----
#pragma unroll 1
        for (int sub = 0; sub < 4; ++sub) {
            const float ts = (sub == 0) ? t0 : (sub == 3 ? t1 : tmid);
            const float* zi = (sub == 0) ? z_s : zin_s;

            // GEMM1 (full K, no split) + fused tanh epilogue -> h_s plain
            {
                u64 a0[ROWS], a1[ROWS];
                gemm1_acc<DZc>(zi, g_W1p, a0, a1);
                const float w0 = wt_s[c0] * ts, w1 = wt_s[c0 + 1] * ts;
#pragma unroll
                for (int r = 0; r < ROWS; ++r) {
                    const float2 v0  = unpack2(a0[r]);
                    const float2 v1  = unpack2(a1[r]);
                    const float2 xbv = *(const float2*)(xb_s + r * DHc + c0);
                    const float h0 = fast_tanh(v0.x + v0.y + xbv.x + w0);
                    const float h1 = fast_tanh(v1.x + v1.y + xbv.y + w1);
                    *(float2*)(h_s + r * DHc + c0) = make_float2(h0, h1);
                }
            }
            __syncthreads();

            // GEMM2 (split-K 4-way, k-packed): thread = (kseg, col pair j0..j0+1)
            {
                const int kseg = tid >> 7;          // 0..3, constant per warp
                const int j0   = (tid & 127) * 2;
                u64 b0a[ROWS], b1a[ROWS];
#pragma unroll
                for (int r = 0; r < ROWS; ++r) { b0a[r] = 0ull; b1a[r] = 0ull; }

                const float* wb = g_W2p + j0 * 2 + (kseg * 256 >> 1) * (2 * DZc);
#pragma unroll 2
                for (int kk = 0; kk < 256; kk += 4) {
                    const int k = kseg * 256 + kk;
                    const ulonglong2 wA = *(const ulonglong2*)(wb + (kk >> 1) * (2 * DZc));
                    const ulonglong2 wB = *(const ulonglong2*)(wb + ((kk >> 1) + 1) * (2 * DZc));
#pragma unroll
                    for (int r = 0; r < ROWS; ++r) {
                        const ulonglong2 hp = *(const ulonglong2*)(h_s + r * DHc + k);  // broadcast
                        fma2(b0a[r], hp.x, wA.x);
                        fma2(b1a[r], hp.x, wA.y);
                        fma2(b0a[r], hp.y, wB.x);
                        fma2(b1a[r], hp.y, wB.y);
                    }
                }
#pragma unroll
                for (int r = 0; r < ROWS; ++r) {
                    const float2 v0 = unpack2(b0a[r]);
                    const float2 v1 = unpack2(b1a[r]);
                    *(float2*)(part_s + kseg * (ROWS * DZc) + r * DZc + j0) =
                        make_float2(v0.x + v0.y, v1.x + v1.y);
                }
            }
            __syncthreads();

            // combine 4 partials + RK4 update (thread owns row r, cols j4..j4+3)
            {
                const int r  = tid >> 6;
                const int j4 = (tid & 63) * 4;
                const int base = r * DZc + j4;
                float4 s = *(const float4*)(part_s + base);
#pragma unroll
                for (int seg = 1; seg < 4; ++seg) {
                    const float4 p = *(const float4*)(part_s + seg * (ROWS * DZc) + base);
                    s.x += p.x; s.y += p.y; s.z += p.z; s.w += p.w;
                }
                const float4 bb = *(const float4*)(b2_s + j4);
                const float v0 = s.x + bb.x, v1 = s.y + bb.y;
                const float v2 = s.z + bb.z, v3 = s.w + bb.w;

                const float4 zv = *(const float4*)(z_s + base);

                if (sub == 0) {
                    *(float4*)(ksum_s + base) = make_float4(v0, v1, v2, v3);
                    const float c = 0.5f * hstep;
                    *(float4*)(zin_s + base) =
                        make_float4(zv.x + c * v0, zv.y + c * v1, zv.z + c * v2, zv.w + c * v3);
                } else if (sub == 1 || sub == 2) {
                    float4 ks = *(const float4*)(ksum_s + base);
                    ks.x += 2.f * v0; ks.y += 2.f * v1;
                    ks.z += 2.f * v2; ks.w += 2.f * v3;
                    *(float4*)(ksum_s + base) = ks;
                    const float c = (sub == 1) ? 0.5f * hstep : hstep;
                    *(float4*)(zin_s + base) =
                        make_float4(zv.x + c * v0, zv.y + c * v1, zv.z + c * v2, zv.w + c * v3);
                } else {
                    const float4 ks = *(const float4*)(ksum_s + base);
                    const float c = hstep * (1.f / 6.f);
                    *(float4*)(z_s + base) =
                        make_float4(zv.x + c * (ks.x + v0), zv.y + c * (ks.y + v1),
                                    zv.z + c * (ks.z + v2), zv.w + c * (ks.w + v3));
                }
            }
            __syncthreads();
        }
    }

    // write z_final
#pragma unroll
    for (int i = 0; i < (ROWS * DZc) / NTH; ++i)
        out[row0 * DZc + i * NTH + tid] = z_s[i * NTH + tid];
}

extern "C" void kernel_launch(void* const* d_in, const int* in_sizes, int n_in,
                              void* d_out, int out_size)
{
    const float* z0 = (const float*)d_in[0];
    const float* t  = (const float*)d_in[1];
    const float* x  = (const float*)d_in[2];
    const float* W1 = (const float*)d_in[3];
    const float* Wx = (const float*)d_in[4];
    const float* wt = (const float*)d_in[5];
    const float* b1 = (const float*)d_in[6];
    const float* W2 = (const float*)d_in[7];
    const float* b2 = (const float*)d_in[8];
    float* out = (float*)d_out;

    // pack weights into k-pair-interleaved scratch (stream-ordered before main)
    pack_kernel<<<(DZc * DHc) / 256, 256>>>(W1, Wx, W2);

    const size_t smem = SMEM_FLOATS * sizeof(float);   // ~131 KB
    cudaFuncSetAttribute(ode_kernel,
                         cudaFuncAttributeMaxDynamicSharedMemorySize, (int)smem);
    ode_kernel<<<NCTA, NTH, smem>>>(z0, t, x, wt, b1, b2, out);
}

// round 8
// speedup vs baseline: 1.1050x; 1.0201x over previous
#include <cuda_runtime.h>

// Problem constants
#define TT   64
#define BB   1024
#define DZc  256
#define DXc  64
#define DHc  1024

#define ROWS 8                 // batch rows per CTA
#define NCTA (BB / ROWS)       // 128 CTAs
#define NTH  512               // threads per CTA (16 warps)

// Packed weight scratch (k-pair interleaved): W*[k][c] -> Wp[k/2][c][2]
__device__ float g_W1p[DZc * DHc];   // 1 MB
__device__ float g_Wxp[DXc * DHc];   // 256 KB
__device__ float g_W2p[DHc * DZc];   // 1 MB

// Dynamic shared memory layout (floats)
#define OFF_Z    0                             // 2048
#define OFF_ZIN  (OFF_Z    + ROWS * DZc)       // 2048
#define OFF_KSUM (OFF_ZIN  + ROWS * DZc)       // 2048
#define OFF_XB   (OFF_KSUM + ROWS * DZc)       // 8192
#define OFF_H    (OFF_XB   + ROWS * DHc)       // 8192 (plain layout)
#define OFF_PART (OFF_H    + ROWS * DHc)       // 4 * 2048 = 8192
#define OFF_XS   (OFF_PART + 4 * ROWS * DZc)   // 512
#define OFF_WT   (OFF_XS   + ROWS * DXc)       // 1024
#define OFF_B1   (OFF_WT   + DHc)              // 1024
#define OFF_B2   (OFF_B1   + DHc)              // 256
#define SMEM_FLOATS (OFF_B2 + DZc)             // 33536 floats = 131 KB

typedef unsigned long long u64;

// packed f32x2 FMA: acc(2 lanes) += a * b
__device__ __forceinline__ void fma2(u64& acc, u64 a, u64 b)
{
    asm("fma.rn.f32x2 %0, %1, %2, %0;" : "+l"(acc) : "l"(a), "l"(b));
}
__device__ __forceinline__ float2 unpack2(u64 p)
{
    float2 v;
    asm("mov.b64 {%0, %1}, %2;" : "=f"(v.x), "=f"(v.y) : "l"(p));
    return v;
}

// 1 - 2/(1+e^{2x}); saturates correctly at +/-inf of exp.
__device__ __forceinline__ float fast_tanh(float x)
{
    const float e = __expf(2.0f * x);
    return 1.0f - 2.0f * __fdividef(1.0f, 1.0f + e);
}

// ---------------------------------------------------------------------------
// Weight pack kernel: Wp[kp][c][2] = (W[2kp][c], W[2kp+1][c])
// ---------------------------------------------------------------------------
__global__ void pack_kernel(const float* __restrict__ W1,
                            const float* __restrict__ Wx,
                            const float* __restrict__ W2)
{
    const int i = blockIdx.x * blockDim.x + threadIdx.x;   // [0, 262144)
    {   // W1p: row = 2048 floats (1024 cols x 2)
        const int kp = i >> 11, rem = i & 2047;
        const int c = rem >> 1, par = rem & 1;
        g_W1p[i] = W1[(2 * kp + par) * DHc + c];
    }
    {   // W2p: row = 512 floats (256 cols x 2)
        const int kp = i >> 9, rem = i & 511;
        const int j = rem >> 1, par = rem & 1;
        g_W2p[i] = W2[(2 * kp + par) * DZc + j];
    }
    if (i < DXc * DHc) {   // Wxp
        const int kp = i >> 11, rem = i & 2047;
        const int c = rem >> 1, par = rem & 1;
        g_Wxp[i] = Wx[(2 * kp + par) * DHc + c];
    }
}

// ---------------------------------------------------------------------------
// k-packed GEMM accumulate: thread owns cols (c0, c0+1), all 8 rows, full K.
// in_s plain [r][KTOT]; Wp packed [kp][1024][2].  acc lanes = (even-k, odd-k).
// unroll 4: ptxas front-batches 8 LDG.128 (MLP~8) to cover ~250cyc L2 latency.
// ---------------------------------------------------------------------------
template <int KTOT>
__device__ __forceinline__ void gemm1_acc(
    const float* in_s, const float* __restrict__ Wp, u64* a0, u64* a1)
{
    const int c0 = threadIdx.x * 2;
#pragma unroll
    for (int r = 0; r < ROWS; ++r) { a0[r] = 0ull; a1[r] = 0ull; }

    const float* wb = Wp + c0 * 2;
#pragma unroll 4
    for (int k = 0; k < KTOT; k += 4) {
        // wA: kpair(k,k+1) for cols c0,c1 ; wB: kpair(k+2,k+3)
        const ulonglong2 wA = *(const ulonglong2*)(wb + (k >> 1) * (2 * DHc));
        const ulonglong2 wB = *(const ulonglong2*)(wb + ((k >> 1) + 1) * (2 * DHc));
#pragma unroll
        for (int r = 0; r < ROWS; ++r) {
            const ulonglong2 zp = *(const ulonglong2*)(in_s + r * KTOT + k);  // broadcast
            fma2(a0[r], zp.x, wA.x);
            fma2(a1[r], zp.x, wA.y);
            fma2(a0[r], zp.y, wB.x);
            fma2(a1[r], zp.y, wB.y);
        }
    }
}

// ---------------------------------------------------------------------------
// Persistent kernel
// ---------------------------------------------------------------------------
__global__ void __launch_bounds__(NTH, 1)
ode_kernel(const float* __restrict__ z0, const float* __restrict__ t,
           const float* __restrict__ x,  const float* __restrict__ wt,
           const float* __restrict__ b1, const float* __restrict__ b2,
           float* __restrict__ out)
{
    extern __shared__ float sm[];
    float* z_s    = sm + OFF_Z;
    float* zin_s  = sm + OFF_ZIN;
    float* ksum_s = sm + OFF_KSUM;
    float* xb_s   = sm + OFF_XB;
    float* h_s    = sm + OFF_H;      // plain [r][DH]
    float* part_s = sm + OFF_PART;   // 4 segs of [r][DZ]
    float* xs_s   = sm + OFF_XS;     // plain [r][DX]
    float* wt_s   = sm + OFF_WT;
    float* b1_s   = sm + OFF_B1;
    float* b2_s   = sm + OFF_B2;

    const int tid  = threadIdx.x;
    const int c0   = tid * 2;        // GEMM1 column pair
    const int row0 = blockIdx.x * ROWS;

    // cache small vectors; load z0 block
    wt_s[tid]       = wt[tid];
    wt_s[tid + NTH] = wt[tid + NTH];
    b1_s[tid]       = b1[tid];
    b1_s[tid + NTH] = b1[tid + NTH];
    if (tid < DZc) b2_s[tid] = b2[tid];
#pragma unroll
    for (int i = 0; i < (ROWS * DZc) / NTH; ++i)
        z_s[i * NTH + tid] = z0[row0 * DZc + i * NTH + tid];
    __syncthreads();

    for (int step = 0; step < TT - 1; ++step) {
        const float t0 = __ldg(t + step);
        const float t1 = __ldg(t + step + 1);
        const float hstep = t1 - t0;
        const float tmid  = t0 + 0.5f * hstep;

        // stage x[step] rows plain [r][DX]
        xs_s[tid] = x[(step * BB + row0) * DXc + tid];
        __syncthreads();

        // ---- xb = x @ Wx + b1 (no split; epilogue writes xb_s directly) ----
        {
            u64 a0[ROWS], a1[ROWS];
            gemm1_acc<DXc>(xs_s, g_Wxp, a0, a1);
            const float bb0 = b1_s[c0], bb1 = b1_s[c0 + 1];
#pragma unroll
            for (int r = 0; r < ROWS; ++r) {
                const float2 v0 = unpack2(a0[r]);
                const float2 v1 = unpack2(a1[r]);
                *(float2*)(xb_s + r * DHc + c0) =
                    make_float2(v0.x + v0.y + bb0, v1.x + v1.y + bb1);
            }
        }
        __syncthreads();

        // ---- 4 RK4 sub-evaluations ----
#pragma unroll 1
        for (int sub = 0; sub < 4; ++sub) {
            const float ts = (sub == 0) ? t0 : (sub == 3 ? t1 : tmid);
            const float* zi = (sub == 0) ? z_s : zin_s;

            // GEMM1 (full K, no split) + fused tanh epilogue -> h_s plain
            {
                u64 a0[ROWS], a1[ROWS];
                gemm1_acc<DZc>(zi, g_W1p, a0, a1);
                const float w0 = wt_s[c0] * ts, w1 = wt_s[c0 + 1] * ts;
#pragma unroll
                for (int r = 0; r < ROWS; ++r) {
                    const float2 v0  = unpack2(a0[r]);
                    const float2 v1  = unpack2(a1[r]);
                    const float2 xbv = *(const float2*)(xb_s + r * DHc + c0);
                    const float h0 = fast_tanh(v0.x + v0.y + xbv.x + w0);
                    const float h1 = fast_tanh(v1.x + v1.y + xbv.y + w1);
                    *(float2*)(h_s + r * DHc + c0) = make_float2(h0, h1);
                }
            }
            __syncthreads();

            // GEMM2 (split-K 4-way, k-packed): thread = (kseg, col pair j0..j0+1)
            {
                const int kseg = tid >> 7;          // 0..3, constant per warp
                const int j0   = (tid & 127) * 2;
                u64 b0a[ROWS], b1a[ROWS];
#pragma unroll
                for (int r = 0; r < ROWS; ++r) { b0a[r] = 0ull; b1a[r] = 0ull; }

                const float* wb = g_W2p + j0 * 2 + (kseg * 256 >> 1) * (2 * DZc);
#pragma unroll 4
                for (int kk = 0; kk < 256; kk += 4) {
                    const int k = kseg * 256 + kk;
                    const ulonglong2 wA = *(const ulonglong2*)(wb + (kk >> 1) * (2 * DZc));
                    const ulonglong2 wB = *(const ulonglong2*)(wb + ((kk >> 1) + 1) * (2 * DZc));
#pragma unroll
                    for (int r = 0; r < ROWS; ++r) {
                        const ulonglong2 hp = *(const ulonglong2*)(h_s + r * DHc + k);  // broadcast
                        fma2(b0a[r], hp.x, wA.x);
                        fma2(b1a[r], hp.x, wA.y);
                        fma2(b0a[r], hp.y, wB.x);
                        fma2(b1a[r], hp.y, wB.y);
                    }
                }
#pragma unroll
                for (int r = 0; r < ROWS; ++r) {
                    const float2 v0 = unpack2(b0a[r]);
                    const float2 v1 = unpack2(b1a[r]);
                    *(float2*)(part_s + kseg * (ROWS * DZc) + r * DZc + j0) =
                        make_float2(v0.x + v0.y, v1.x + v1.y);
                }
            }
            __syncthreads();

            // combine 4 partials + RK4 update (thread owns row r, cols j4..j4+3)
            {
                const int r  = tid >> 6;
                const int j4 = (tid & 63) * 4;
                const int base = r * DZc + j4;
                float4 s = *(const float4*)(part_s + base);
#pragma unroll
                for (int seg = 1; seg < 4; ++seg) {
                    const float4 p = *(const float4*)(part_s + seg * (ROWS * DZc) + base);
                    s.x += p.x; s.y += p.y; s.z += p.z; s.w += p.w;
                }
                const float4 bb = *(const float4*)(b2_s + j4);
                const float v0 = s.x + bb.x, v1 = s.y + bb.y;
                const float v2 = s.z + bb.z, v3 = s.w + bb.w;

                const float4 zv = *(const float4*)(z_s + base);

                if (sub == 0) {
                    *(float4*)(ksum_s + base) = make_float4(v0, v1, v2, v3);
                    const float c = 0.5f * hstep;
                    *(float4*)(zin_s + base) =
                        make_float4(zv.x + c * v0, zv.y + c * v1, zv.z + c * v2, zv.w + c * v3);
                } else if (sub == 1 || sub == 2) {
                    float4 ks = *(const float4*)(ksum_s + base);
                    ks.x += 2.f * v0; ks.y += 2.f * v1;
                    ks.z += 2.f * v2; ks.w += 2.f * v3;
                    *(float4*)(ksum_s + base) = ks;
                    const float c = (sub == 1) ? 0.5f * hstep : hstep;
                    *(float4*)(zin_s + base) =
                        make_float4(zv.x + c * v0, zv.y + c * v1, zv.z + c * v2, zv.w + c * v3);
                } else {
                    const float4 ks = *(const float4*)(ksum_s + base);
                    const float c = hstep * (1.f / 6.f);
                    *(float4*)(z_s + base) =
                        make_float4(zv.x + c * (ks.x + v0), zv.y + c * (ks.y + v1),
                                    zv.z + c * (ks.z + v2), zv.w + c * (ks.w + v3));
                }
            }
            __syncthreads();
        }
    }

    // write z_final
#pragma unroll
    for (int i = 0; i < (ROWS * DZc) / NTH; ++i)
        out[row0 * DZc + i * NTH + tid] = z_s[i * NTH + tid];
}

extern "C" void kernel_launch(void* const* d_in, const int* in_sizes, int n_in,
                              void* d_out, int out_size)
{
    const float* z0 = (const float*)d_in[0];
    const float* t  = (const float*)d_in[1];
    const float* x  = (const float*)d_in[2];
    const float* W1 = (const float*)d_in[3];
    const float* Wx = (const float*)d_in[4];
    const float* wt = (const float*)d_in[5];
    const float* b1 = (const float*)d_in[6];
    const float* W2 = (const float*)d_in[7];
    const float* b2 = (const float*)d_in[8];
    float* out = (float*)d_out;

    // pack weights into k-pair-interleaved scratch (stream-ordered before main)
    pack_kernel<<<(DZc * DHc) / 256, 256>>>(W1, Wx, W2);

    const size_t smem = SMEM_FLOATS * sizeof(float);   // ~131 KB
    cudaFuncSetAttribute(ode_kernel,
                         cudaFuncAttributeMaxDynamicSharedMemorySize, (int)smem);
    ode_kernel<<<NCTA, NTH, smem>>>(z0, t, x, wt, b1, b2, out);
}

// round 9
// speedup vs baseline: 1.1338x; 1.0261x over previous
#include <cuda_runtime.h>

// Problem constants
#define TT   64
#define BB   1024
#define DZc  256
#define DXc  64
#define DHc  1024

#define ROWS 8                 // batch rows per CTA
#define NCTA (BB / ROWS)       // 128 CTAs
#define NTH  512               // threads per CTA (16 warps = 4 groups of 4)

// Packed weight scratch (k-pair interleaved): W*[k][c] -> Wp[k/2][c][2]
__device__ float g_W1p[DZc * DHc];   // 1 MB
__device__ float g_Wxp[DXc * DHc];   // 256 KB
__device__ float g_W2p[DHc * DZc];   // 1 MB

// Dynamic shared memory layout (floats)
#define OFF_Z    0                             // 2048
#define OFF_ZIN  (OFF_Z    + ROWS * DZc)       // 2048
#define OFF_KSUM (OFF_ZIN  + ROWS * DZc)       // 2048
#define OFF_XB   (OFF_KSUM + ROWS * DZc)       // 8192
#define OFF_H    (OFF_XB   + ROWS * DHc)       // 8192 (plain layout)
#define OFF_PART (OFF_H    + ROWS * DHc)       // 4 * 2048 = 8192
#define OFF_XS   (OFF_PART + 4 * ROWS * DZc)   // 512
#define OFF_WT   (OFF_XS   + ROWS * DXc)       // 1024
#define OFF_B1   (OFF_WT   + DHc)              // 1024
#define OFF_B2   (OFF_B1   + DHc)              // 256
#define SMEM_FLOATS (OFF_B2 + DZc)             // 33536 floats = 131 KB

typedef unsigned long long u64;

// packed f32x2 FMA: acc(2 lanes) += a * b
__device__ __forceinline__ void fma2(u64& acc, u64 a, u64 b)
{
    asm("fma.rn.f32x2 %0, %1, %2, %0;" : "+l"(acc) : "l"(a), "l"(b));
}
__device__ __forceinline__ float2 unpack2(u64 p)
{
    float2 v;
    asm("mov.b64 {%0, %1}, %2;" : "=f"(v.x), "=f"(v.y) : "l"(p));
    return v;
}

// group-local barrier: 128 threads of warp-group g sync on named barrier g+1
__device__ __forceinline__ void group_bar(int g)
{
    asm volatile("bar.sync %0, 128;" :: "r"(g + 1) : "memory");
}

// 1 - 2/(1+e^{2x}); saturates correctly at +/-inf of exp.
__device__ __forceinline__ float fast_tanh(float x)
{
    const float e = __expf(2.0f * x);
    return 1.0f - 2.0f * __fdividef(1.0f, 1.0f + e);
}

// ---------------------------------------------------------------------------
// Weight pack kernel: Wp[kp][c][2] = (W[2kp][c], W[2kp+1][c])
// ---------------------------------------------------------------------------
__global__ void pack_kernel(const float* __restrict__ W1,
                            const float* __restrict__ Wx,
                            const float* __restrict__ W2)
{
    const int i = blockIdx.x * blockDim.x + threadIdx.x;   // [0, 262144)
    {   // W1p: row = 2048 floats (1024 cols x 2)
        const int kp = i >> 11, rem = i & 2047;
        const int c = rem >> 1, par = rem & 1;
        g_W1p[i] = W1[(2 * kp + par) * DHc + c];
    }
    {   // W2p: row = 512 floats (256 cols x 2)
        const int kp = i >> 9, rem = i & 511;
        const int j = rem >> 1, par = rem & 1;
        g_W2p[i] = W2[(2 * kp + par) * DZc + j];
    }
    if (i < DXc * DHc) {   // Wxp
        const int kp = i >> 11, rem = i & 2047;
        const int c = rem >> 1, par = rem & 1;
        g_Wxp[i] = Wx[(2 * kp + par) * DHc + c];
    }
}

// ---------------------------------------------------------------------------
// k-packed GEMM accumulate: thread owns cols (c0, c0+1), all 8 rows, full K.
// in_s plain [r][KTOT]; Wp packed [kp][1024][2].  acc lanes = (even-k, odd-k).
// ---------------------------------------------------------------------------
template <int KTOT>
__device__ __forceinline__ void gemm1_acc(
    int c0, const float* in_s, const float* __restrict__ Wp, u64* a0, u64* a1)
{
#pragma unroll
    for (int r = 0; r < ROWS; ++r) { a0[r] = 0ull; a1[r] = 0ull; }

    const float* wb = Wp + c0 * 2;
#pragma unroll 4
    for (int k = 0; k < KTOT; k += 4) {
        // wA: kpair(k,k+1) for cols c0,c1 ; wB: kpair(k+2,k+3)
        const ulonglong2 wA = *(const ulonglong2*)(wb + (k >> 1) * (2 * DHc));
        const ulonglong2 wB = *(const ulonglong2*)(wb + ((k >> 1) + 1) * (2 * DHc));
#pragma unroll
        for (int r = 0; r < ROWS; ++r) {
            const ulonglong2 zp = *(const ulonglong2*)(in_s + r * KTOT + k);  // broadcast
            fma2(a0[r], zp.x, wA.x);
            fma2(a1[r], zp.x, wA.y);
            fma2(a0[r], zp.y, wB.x);
            fma2(a1[r], zp.y, wB.y);
        }
    }
}

// ---------------------------------------------------------------------------
// Persistent kernel.  Warp-group g (threads [128g,128g+128)) owns:
//   GEMM1 cols [256g, 256g+256)  ->  h columns of its own k-segment
//   GEMM2 kseg g (k in [256g, 256g+256))  -- reads only ITS OWN h columns.
// So GEMM1->GEMM2 needs only a group-local named barrier; h never crosses
// groups.  Groups skew freely between the two global syncs per sub-eval,
// overlapping LDG-heavy and LDS-heavy phases on l1tex.
// ---------------------------------------------------------------------------
__global__ void __launch_bounds__(NTH, 1)
ode_kernel(const float* __restrict__ z0, const float* __restrict__ t,
           const float* __restrict__ x,  const float* __restrict__ wt,
           const float* __restrict__ b1, const float* __restrict__ b2,
           float* __restrict__ out)
{
    extern __shared__ float sm[];
    float* z_s    = sm + OFF_Z;
    float* zin_s  = sm + OFF_ZIN;
    float* ksum_s = sm + OFF_KSUM;
    float* xb_s   = sm + OFF_XB;
    float* h_s    = sm + OFF_H;      // plain [r][DH]; group-private col bands
    float* part_s = sm + OFF_PART;   // 4 segs of [r][DZ]
    float* xs_s   = sm + OFF_XS;     // plain [r][DX]
    float* wt_s   = sm + OFF_WT;
    float* b1_s   = sm + OFF_B1;
    float* b2_s   = sm + OFF_B2;

    const int tid  = threadIdx.x;
    const int grp  = tid >> 7;             // warp-group 0..3
    const int lg   = tid & 127;            // lane within group
    const int c0   = grp * 256 + lg * 2;   // GEMM1 column pair (group band)
    const int j0   = lg * 2;               // GEMM2 column pair
    const int row0 = blockIdx.x * ROWS;

    // cache small vectors; load z0 block
    wt_s[tid]       = wt[tid];
    wt_s[tid + NTH] = wt[tid + NTH];
    b1_s[tid]       = b1[tid];
    b1_s[tid + NTH] = b1[tid + NTH];
    if (tid < DZc) b2_s[tid] = b2[tid];
#pragma unroll
    for (int i = 0; i < (ROWS * DZc) / NTH; ++i)
        z_s[i * NTH + tid] = z0[row0 * DZc + i * NTH + tid];
    __syncthreads();

    for (int step = 0; step < TT - 1; ++step) {
        const float t0 = __ldg(t + step);
        const float t1 = __ldg(t + step + 1);
        const float hstep = t1 - t0;
        const float tmid  = t0 + 0.5f * hstep;

        // stage x[step] rows plain [r][DX]
        xs_s[tid] = x[(step * BB + row0) * DXc + tid];
        __syncthreads();

        // ---- xb = x @ Wx + b1 (group-banded cols; epilogue direct) ----
        {
            u64 a0[ROWS], a1[ROWS];
            gemm1_acc<DXc>(c0, xs_s, g_Wxp, a0, a1);
            const float bb0 = b1_s[c0], bb1 = b1_s[c0 + 1];
#pragma unroll
            for (int r = 0; r < ROWS; ++r) {
                const float2 v0 = unpack2(a0[r]);
                const float2 v1 = unpack2(a1[r]);
                *(float2*)(xb_s + r * DHc + c0) =
                    make_float2(v0.x + v0.y + bb0, v1.x + v1.y + bb1);
            }
        }
        __syncthreads();

        // ---- 4 RK4 sub-evaluations ----
#pragma unroll 1
        for (int sub = 0; sub < 4; ++sub) {
            const float ts = (sub == 0) ? t0 : (sub == 3 ? t1 : tmid);
            const float* zi = (sub == 0) ? z_s : zin_s;

            // GEMM1 (group col band) + fused tanh epilogue -> h_s band
            {
                u64 a0[ROWS], a1[ROWS];
                gemm1_acc<DZc>(c0, zi, g_W1p, a0, a1);
                const float w0 = wt_s[c0] * ts, w1 = wt_s[c0 + 1] * ts;
#pragma unroll
                for (int r = 0; r < ROWS; ++r) {
                    const float2 v0  = unpack2(a0[r]);
                    const float2 v1  = unpack2(a1[r]);
                    const float2 xbv = *(const float2*)(xb_s + r * DHc + c0);
                    const float h0 = fast_tanh(v0.x + v0.y + xbv.x + w0);
                    const float h1 = fast_tanh(v1.x + v1.y + xbv.y + w1);
                    *(float2*)(h_s + r * DHc + c0) = make_float2(h0, h1);
                }
            }
            group_bar(grp);    // only this group's h band is needed below

            // GEMM2 kseg = grp (k-packed): reads h[r][256g .. 256g+256)
            {
                u64 b0a[ROWS], b1a[ROWS];
#pragma unroll
                for (int r = 0; r < ROWS; ++r) { b0a[r] = 0ull; b1a[r] = 0ull; }

                const int kb = grp * 256;
                const float* wb = g_W2p + j0 * 2 + (kb >> 1) * (2 * DZc);
#pragma unroll 4
                for (int kk = 0; kk < 256; kk += 4) {
                    const int k = kb + kk;
                    const ulonglong2 wA = *(const ulonglong2*)(wb + (kk >> 1) * (2 * DZc));
                    const ulonglong2 wB = *(const ulonglong2*)(wb + ((kk >> 1) + 1) * (2 * DZc));
#pragma unroll
                    for (int r = 0; r < ROWS; ++r) {
                        const ulonglong2 hp = *(const ulonglong2*)(h_s + r * DHc + k);  // broadcast
                        fma2(b0a[r], hp.x, wA.x);
                        fma2(b1a[r], hp.x, wA.y);
                        fma2(b0a[r], hp.y, wB.x);
                        fma2(b1a[r], hp.y, wB.y);
                    }
                }
#pragma unroll
                for (int r = 0; r < ROWS; ++r) {
                    const float2 v0 = unpack2(b0a[r]);
                    const float2 v1 = unpack2(b1a[r]);
                    *(float2*)(part_s + grp * (ROWS * DZc) + r * DZc + j0) =
                        make_float2(v0.x + v0.y, v1.x + v1.y);
                }
            }
            __syncthreads();   // all groups' partials ready

            // combine 4 partials + RK4 update (thread owns row r, cols j4..j4+3)
            {
                const int r  = tid >> 6;
                const int j4 = (tid & 63) * 4;
                const int base = r * DZc + j4;
                float4 s = *(const float4*)(part_s + base);
#pragma unroll
                for (int seg = 1; seg < 4; ++seg) {
                    const float4 p = *(const float4*)(part_s + seg * (ROWS * DZc) + base);
                    s.x += p.x; s.y += p.y; s.z += p.z; s.w += p.w;
                }
                const float4 bb = *(const float4*)(b2_s + j4);
                const float v0 = s.x + bb.x, v1 = s.y + bb.y;
                const float v2 = s.z + bb.z, v3 = s.w + bb.w;

                const float4 zv = *(const float4*)(z_s + base);

                if (sub == 0) {
                    *(float4*)(ksum_s + base) = make_float4(v0, v1, v2, v3);
                    const float c = 0.5f * hstep;
                    *(float4*)(zin_s + base) =
                        make_float4(zv.x + c * v0, zv.y + c * v1, zv.z + c * v2, zv.w + c * v3);
                } else if (sub == 1 || sub == 2) {
                    float4 ks = *(const float4*)(ksum_s + base);
                    ks.x += 2.f * v0; ks.y += 2.f * v1;
                    ks.z += 2.f * v2; ks.w += 2.f * v3;
                    *(float4*)(ksum_s + base) = ks;
                    const float c = (sub == 1) ? 0.5f * hstep : hstep;
                    *(float4*)(zin_s + base) =
                        make_float4(zv.x + c * v0, zv.y + c * v1, zv.z + c * v2, zv.w + c * v3);
                } else {
                    const float4 ks = *(const float4*)(ksum_s + base);
                    const float c = hstep * (1.f / 6.f);
                    *(float4*)(z_s + base) =
                        make_float4(zv.x + c * (ks.x + v0), zv.y + c * (ks.y + v1),
                                    zv.z + c * (ks.z + v2), zv.w + c * (ks.w + v3));
                }
            }
            __syncthreads();   // zin/z complete for next sub-eval
        }
    }

    // write z_final
#pragma unroll
    for (int i = 0; i < (ROWS * DZc) / NTH; ++i)
        out[row0 * DZc + i * NTH + tid] = z_s[i * NTH + tid];
}

extern "C" void kernel_launch(void* const* d_in, const int* in_sizes, int n_in,
                              void* d_out, int out_size)
{
    const float* z0 = (const float*)d_in[0];
    const float* t  = (const float*)d_in[1];
    const float* x  = (const float*)d_in[2];
    const float* W1 = (const float*)d_in[3];
    const float* Wx = (const float*)d_in[4];
    const float* wt = (const float*)d_in[5];
    const float* b1 = (const float*)d_in[6];
    const float* W2 = (const float*)d_in[7];
    const float* b2 = (const float*)d_in[8];
    float* out = (float*)d_out;

    // pack weights into k-pair-interleaved scratch (stream-ordered before main)
    pack_kernel<<<(DZc * DHc) / 256, 256>>>(W1, Wx, W2);

    const size_t smem = SMEM_FLOATS * sizeof(float);   // ~131 KB
    cudaFuncSetAttribute(ode_kernel,
                         cudaFuncAttributeMaxDynamicSharedMemorySize, (int)smem);
    ode_kernel<<<NCTA, NTH, smem>>>(z0, t, x, wt, b1, b2, out);
}